// round 10
// baseline (speedup 1.0000x reference)
#include <cuda_runtime.h>
#include <cuda_bf16.h>
#include <cstdint>

#define N_NODES 50000
#define E_EDGES 1600000
#define IN_F 512
#define HID 64
#define OUT_F 7
#define KSTEPS 32                // 512 / 16
#define NTILES 8                 // 64 / 8
#define NSCANB 196               // ceil(50000 / 256)
#define GBLOCKS 782              // ceil(50000 / 64) gemm blocks (64 rows each)

// ---------------- scratch (static device globals; no allocation) -------------
__device__ float g_dinv[N_NODES];
__device__ int   g_count[N_NODES];
__device__ int   g_rowstart[N_NODES + 1];
__device__ int   g_cursor[N_NODES];
__device__ int   g_srcs[E_EDGES];
__device__ float g_h1[(size_t)N_NODES * HID];    // x @ W1
__device__ float g_h2[(size_t)N_NODES * 8];      // relu(agg1+b1) @ W2, stride 8
__device__ int   g_is64;                         // edge_index dtype flag
__device__ int   g_blocksum[NSCANB];
__device__ int   g_blockoff[NSCANB];
// Pre-packed W1 fragments, layout [ks][nt][lane], K-permuted (see w1 pack)
__device__ uint2 g_bfragH[KSTEPS * NTILES * 32];
__device__ uint2 g_bfragL[KSTEPS * NTILES * 32];

// ---------------- helpers ----------------------------------------------------
__device__ __forceinline__ void mma16816(float* d, const uint32_t* a, const uint32_t b0,
                                         const uint32_t b1) {
    asm volatile(
        "mma.sync.aligned.m16n8k16.row.col.f32.bf16.bf16.f32 "
        "{%0,%1,%2,%3}, {%4,%5,%6,%7}, {%8,%9}, {%0,%1,%2,%3};"
        : "+f"(d[0]), "+f"(d[1]), "+f"(d[2]), "+f"(d[3])
        : "r"(a[0]), "r"(a[1]), "r"(a[2]), "r"(a[3]), "r"(b0), "r"(b1));
}

// fast split: hi = bf16x2(fa@lo, fb@hi); lo = residuals
__device__ __forceinline__ void cvt_pair(float fa, float fb, uint32_t& hi, uint32_t& lo) {
    asm("cvt.rn.bf16x2.f32 %0, %1, %2;" : "=r"(hi) : "f"(fb), "f"(fa));
    float ra = __uint_as_float(hi << 16);
    float rb = __uint_as_float(hi & 0xffff0000u);
    float la = fa - ra, lb = fb - rb;
    asm("cvt.rn.bf16x2.f32 %0, %1, %2;" : "=r"(lo) : "f"(lb), "f"(la));
}

__device__ __forceinline__ void cp_async16(uint32_t saddr, const void* g) {
    asm volatile("cp.async.ca.shared.global [%0], [%1], 16;" :: "r"(saddr), "l"(g));
}
#define CP_COMMIT() asm volatile("cp.async.commit_group;" ::: "memory")
#define CP_WAIT2()  asm volatile("cp.async.wait_group 2;" ::: "memory")

// ---------------- setup: zero counts + detect dtype + pack W1 frags ----------
// K-permutation: for kstep ks, lane tg group, virtual k {2tg,2tg+1,2tg+8,2tg+9}
// maps to physical k {kb..kb+3}, kb = ks*16 + tg*4. A-side loads use the same
// permutation, so results are exact.
__global__ void setup_kernel(const float* __restrict__ W1, const int* __restrict__ ei32) {
    int idx = blockIdx.x * blockDim.x + threadIdx.x;
    if (idx < N_NODES) g_count[idx] = 0;
    if (idx < KSTEPS * NTILES * 32) {
        int lane = idx & 31;
        int t    = idx >> 5;
        int nt   = t & 7;
        int ks   = t >> 3;
        int tg = lane & 3, gp = lane >> 2;
        int n  = nt * 8 + gp;
        int kb = ks * 16 + tg * 4;
        float f00 = W1[(size_t)(kb)     * HID + n];
        float f01 = W1[(size_t)(kb + 1) * HID + n];
        float f10 = W1[(size_t)(kb + 2) * HID + n];
        float f11 = W1[(size_t)(kb + 3) * HID + n];
        uint32_t h0, l0, h1, l1;
        cvt_pair(f00, f01, h0, l0);
        cvt_pair(f10, f11, h1, l1);
        g_bfragH[idx] = make_uint2(h0, h1);
        g_bfragL[idx] = make_uint2(l0, l1);
    }
    if (blockIdx.x == 0 && idx < 32) {
        int nz = (ei32[2 * idx + 1] != 0) | (ei32[2 * (idx + 32) + 1] != 0);
        unsigned any = __ballot_sync(0xffffffffu, nz);
        if (idx == 0) g_is64 = (any == 0);
    }
}

__device__ __forceinline__ int load_idx(const int* ei32, long long pos, int is64) {
    if (is64) {
        const long long* p = (const long long*)ei32;
        return (int)p[pos];
    }
    return ei32[pos];
}

// ---------------- degree histogram (4 edges / thread) ------------------------
__global__ void hist_kernel(const int* __restrict__ ei32, int E) {
    int e0 = (blockIdx.x * blockDim.x + threadIdx.x) * 4;
    if (e0 >= E) return;
    int is64 = g_is64;
    int d[4];
    int n = min(4, E - e0);
    if (n == 4 && (E & 3) == 0) {
        if (is64) {
            const longlong2* p = (const longlong2*)((const long long*)ei32 + E + e0);
            longlong2 v0 = p[0], v1 = p[1];
            d[0] = (int)v0.x; d[1] = (int)v0.y; d[2] = (int)v1.x; d[3] = (int)v1.y;
        } else {
            int4 v = *(const int4*)(ei32 + E + e0);
            d[0] = v.x; d[1] = v.y; d[2] = v.z; d[3] = v.w;
        }
    } else {
        for (int i = 0; i < 4; i++)
            d[i] = (i < n) ? load_idx(ei32, (long long)E + e0 + i, is64) : -1;
    }
#pragma unroll
    for (int i = 0; i < 4; i++) {
        unsigned dd = (unsigned)d[i];
        if (dd < N_NODES) atomicAdd(&g_count[dd], 1);
    }
}

// ---------------- 3-phase parallel exclusive scan ----------------------------
__global__ void scanA_kernel() {            // per-block reduction of counts
    __shared__ int red[256];
    int i = blockIdx.x * 256 + threadIdx.x;
    int c = (i < N_NODES) ? g_count[i] : 0;
    red[threadIdx.x] = c;
    __syncthreads();
    for (int off = 128; off; off >>= 1) {
        if (threadIdx.x < off) red[threadIdx.x] += red[threadIdx.x + off];
        __syncthreads();
    }
    if (threadIdx.x == 0) g_blocksum[blockIdx.x] = red[0];
}

__global__ void scanB_kernel() {            // scan 196 block sums (1 block)
    __shared__ int s[256];
    int tid = threadIdx.x;
    int v = (tid < NSCANB) ? g_blocksum[tid] : 0;
    s[tid] = v;
    __syncthreads();
    for (int off = 1; off < 256; off <<= 1) {
        int t = (tid >= off) ? s[tid - off] : 0;
        __syncthreads();
        s[tid] += t;
        __syncthreads();
    }
    if (tid < NSCANB) g_blockoff[tid] = s[tid] - v;   // exclusive
}

__global__ void scanC_kernel() {            // block-local scan + apply + dinv
    __shared__ int s[256];
    int tid = threadIdx.x;
    int i = blockIdx.x * 256 + tid;
    int c = (i < N_NODES) ? g_count[i] : 0;
    s[tid] = c;
    __syncthreads();
    for (int off = 1; off < 256; off <<= 1) {
        int t = (tid >= off) ? s[tid - off] : 0;
        __syncthreads();
        s[tid] += t;
        __syncthreads();
    }
    if (i < N_NODES) {
        int excl = g_blockoff[blockIdx.x] + s[tid] - c;
        g_rowstart[i] = excl;
        g_cursor[i]   = excl;
        g_dinv[i]     = rsqrtf((float)(c + 1));       // deg includes self-loop
        if (i == N_NODES - 1) g_rowstart[N_NODES] = excl + c;
    }
}

// ---------------- CSR fill (4 edges / thread) --------------------------------
__global__ void fill_kernel(const int* __restrict__ ei32, int E) {
    int e0 = (blockIdx.x * blockDim.x + threadIdx.x) * 4;
    if (e0 >= E) return;
    int is64 = g_is64;
    int sr[4], d[4];
    int n = min(4, E - e0);
    if (n == 4 && (E & 3) == 0) {
        if (is64) {
            const longlong2* ps = (const longlong2*)((const long long*)ei32 + e0);
            const longlong2* pd = (const longlong2*)((const long long*)ei32 + E + e0);
            longlong2 s0 = ps[0], s1 = ps[1], v0 = pd[0], v1 = pd[1];
            sr[0] = (int)s0.x; sr[1] = (int)s0.y; sr[2] = (int)s1.x; sr[3] = (int)s1.y;
            d[0] = (int)v0.x;  d[1] = (int)v0.y;  d[2] = (int)v1.x;  d[3] = (int)v1.y;
        } else {
            int4 s = *(const int4*)(ei32 + e0);
            int4 v = *(const int4*)(ei32 + E + e0);
            sr[0] = s.x; sr[1] = s.y; sr[2] = s.z; sr[3] = s.w;
            d[0] = v.x;  d[1] = v.y;  d[2] = v.z;  d[3] = v.w;
        }
    } else {
        for (int i = 0; i < 4; i++) {
            sr[i] = (i < n) ? load_idx(ei32, e0 + i, is64) : -1;
            d[i]  = (i < n) ? load_idx(ei32, (long long)E + e0 + i, is64) : -1;
        }
    }
#pragma unroll
    for (int i = 0; i < 4; i++) {
        unsigned ss = (unsigned)sr[i], dd = (unsigned)d[i];
        if (ss < N_NODES && dd < N_NODES) {
            int pos = atomicAdd(&g_cursor[dd], 1);
            if (pos < E_EDGES) g_srcs[pos] = (int)ss;
        }
    }
}

// ---------------- GEMM1 v5: cp.async multistage pipeline ---------------------
// Block = 128 thr (4 warps) = 64 rows. Stage = 64 rows x 32 floats (8KB),
// 4 buffers, depth-3 pipeline. Chunk swizzle pr(row)=((row&1)<<2)|(row>>1)
// keeps cp.async stores and LDS.128 reads conflict-free.
// D = xh*wh + xh*wl + xl*wh, fp32 accumulate (err ~2^-18).
__device__ __forceinline__ void issue_stage(uint32_t sbase, const float* __restrict__ x,
                                            int blockRow0, int kc, int tid) {
#pragma unroll
    for (int j = 0; j < 4; j++) {
        int c   = j * 128 + tid;          // 0..511 16B-chunks
        int row = c >> 3;                 // 0..63
        int col = c & 7;                  // 0..7
        int pr  = ((row & 1) << 2) | ((row >> 1) & 3);
        int gr  = blockRow0 + row;
        if (gr > N_NODES - 1) gr = N_NODES - 1;
        const float* g = x + (size_t)gr * IN_F + kc * 32 + col * 4;
        uint32_t s = sbase + (uint32_t)((row * 8 + (col ^ pr)) * 16);
        cp_async16(s, g);
    }
}

__global__ __launch_bounds__(128) void gemm1_mma_kernel(const float* __restrict__ x) {
    __shared__ float4 sbuf[4 * 512];      // 4 stages x 512 float4 = 32KB
    uint32_t sbase = (uint32_t)__cvta_generic_to_shared(sbuf);

    int tid  = threadIdx.x;
    int w    = tid >> 5;
    int lane = tid & 31;
    int gp   = lane >> 2, tg = lane & 3;
    int blockRow0 = blockIdx.x * 64;
    int r0 = blockRow0 + w * 16 + gp, r1 = r0 + 8;
    int pr = ((gp & 1) << 2) | (gp >> 1);      // same for row gp and gp+8

    float acc[NTILES][4];
#pragma unroll
    for (int nt = 0; nt < NTILES; nt++)
#pragma unroll
        for (int j = 0; j < 4; j++) acc[nt][j] = 0.f;

    // prologue: preload 3 stages
#pragma unroll
    for (int kc = 0; kc < 3; kc++) {
        issue_stage(sbase + kc * 8192, x, blockRow0, kc, tid);
        CP_COMMIT();
    }

    int lrow = (w * 16 + gp) * 8;              // float4 index of row r0 in a stage

    for (int kc = 0; kc < 16; kc++) {
        CP_WAIT2();
        __syncthreads();
        int buf = (kc & 3) * 512;
#pragma unroll
        for (int h = 0; h < 2; h++) {
            int ks = kc * 2 + h;
            int swcol = (h * 4 + tg) ^ pr;
            float4 va = sbuf[buf + lrow + swcol];
            float4 vb = sbuf[buf + lrow + 64 + swcol];

            uint32_t ah[4], al[4];
            cvt_pair(va.x, va.y, ah[0], al[0]);
            cvt_pair(vb.x, vb.y, ah[1], al[1]);
            cvt_pair(va.z, va.w, ah[2], al[2]);
            cvt_pair(vb.z, vb.w, ah[3], al[3]);

            const uint2* fh = &g_bfragH[(ks * NTILES) * 32 + lane];
            const uint2* fl = &g_bfragL[(ks * NTILES) * 32 + lane];
#pragma unroll
            for (int nt = 0; nt < NTILES; nt++) {
                uint2 wh = __ldg(fh + nt * 32);
                uint2 wl = __ldg(fl + nt * 32);
                mma16816(acc[nt], ah, wh.x, wh.y);
                mma16816(acc[nt], ah, wl.x, wl.y);
                mma16816(acc[nt], al, wh.x, wh.y);
            }
        }
        __syncthreads();
        if (kc + 3 < 16)
            issue_stage(sbase + ((kc + 3) & 3) * 8192, x, blockRow0, kc + 3, tid);
        CP_COMMIT();                           // empty group in the tail keeps counts
    }

#pragma unroll
    for (int nt = 0; nt < NTILES; nt++) {
        int c = nt * 8 + tg * 2;
        if (r0 < N_NODES)
            *(float2*)(g_h1 + (size_t)r0 * HID + c) = make_float2(acc[nt][0], acc[nt][1]);
        if (r1 < N_NODES)
            *(float2*)(g_h1 + (size_t)r1 * HID + c) = make_float2(acc[nt][2], acc[nt][3]);
    }
}

// ---------------- gather1: agg1 -> relu(+b1) -> fused @W2 -> h2 --------------
__global__ __launch_bounds__(256) void gather1_kernel(const float* __restrict__ W2,
                                                      const float* __restrict__ b1) {
    int node = (blockIdx.x * blockDim.x + threadIdx.x) >> 5;
    int lane = threadIdx.x & 31;
    if (node >= N_NODES) return;

    float di = g_dinv[node];
    float self_w = di * di;
    float a00 = g_h1[(size_t)node * HID + lane]      * self_w;
    float a01 = g_h1[(size_t)node * HID + 32 + lane] * self_w;
    float a10 = 0.f, a11 = 0.f, a20 = 0.f, a21 = 0.f, a30 = 0.f, a31 = 0.f;

    int beg = g_rowstart[node];
    int end = g_rowstart[node + 1];
    for (int e = beg; e < end; e += 32) {
        int s = 0; float w = 0.f;
        if (e + lane < end) {
            s = g_srcs[e + lane];
            w = g_dinv[s] * di;
        }
        int cnt = min(32, end - e);
        int j = 0;
        for (; j + 4 <= cnt; j += 4) {
            int   s0 = __shfl_sync(0xffffffffu, s, j);
            int   s1 = __shfl_sync(0xffffffffu, s, j + 1);
            int   s2 = __shfl_sync(0xffffffffu, s, j + 2);
            int   s3 = __shfl_sync(0xffffffffu, s, j + 3);
            float w0 = __shfl_sync(0xffffffffu, w, j);
            float w1 = __shfl_sync(0xffffffffu, w, j + 1);
            float w2 = __shfl_sync(0xffffffffu, w, j + 2);
            float w3 = __shfl_sync(0xffffffffu, w, j + 3);
            const float* p0 = g_h1 + (size_t)s0 * HID + lane;
            const float* p1 = g_h1 + (size_t)s1 * HID + lane;
            const float* p2 = g_h1 + (size_t)s2 * HID + lane;
            const float* p3 = g_h1 + (size_t)s3 * HID + lane;
            float x00 = p0[0], x01 = p0[32];
            float x10 = p1[0], x11 = p1[32];
            float x20 = p2[0], x21 = p2[32];
            float x30 = p3[0], x31 = p3[32];
            a00 = fmaf(x00, w0, a00); a01 = fmaf(x01, w0, a01);
            a10 = fmaf(x10, w1, a10); a11 = fmaf(x11, w1, a11);
            a20 = fmaf(x20, w2, a20); a21 = fmaf(x21, w2, a21);
            a30 = fmaf(x30, w3, a30); a31 = fmaf(x31, w3, a31);
        }
        for (; j < cnt; j++) {
            int   ss = __shfl_sync(0xffffffffu, s, j);
            float ww = __shfl_sync(0xffffffffu, w, j);
            a00 = fmaf(g_h1[(size_t)ss * HID + lane],      ww, a00);
            a01 = fmaf(g_h1[(size_t)ss * HID + 32 + lane], ww, a01);
        }
    }

    float v0 = (a00 + a10) + (a20 + a30);
    float v1 = (a01 + a11) + (a21 + a31);
    v0 = fmaxf(v0 + b1[lane],      0.f);
    v1 = fmaxf(v1 + b1[lane + 32], 0.f);

    float acc[OUT_F];
#pragma unroll
    for (int o = 0; o < OUT_F; o++)
        acc[o] = v0 * __ldg(&W2[lane * OUT_F + o]) +
                 v1 * __ldg(&W2[(lane + 32) * OUT_F + o]);
#pragma unroll
    for (int off = 16; off; off >>= 1)
#pragma unroll
        for (int o = 0; o < OUT_F; o++)
            acc[o] += __shfl_xor_sync(0xffffffffu, acc[o], off);

    if (lane == 0) {
#pragma unroll
        for (int o = 0; o < OUT_F; o++) g_h2[(size_t)node * 8 + o] = acc[o];
    }
}

// ---------------- gather2: out = agg2(h2) + b2 -------------------------------
__global__ __launch_bounds__(256) void gather2_kernel(const float* __restrict__ b2,
                                                      float* __restrict__ out) {
    int node = (blockIdx.x * blockDim.x + threadIdx.x) >> 5;
    int lane = threadIdx.x & 31;
    if (node >= N_NODES) return;

    int o = lane & 7;
    int g = lane >> 3;
    float di = g_dinv[node];

    float acc = 0.f;
    if (g == 0 && o < OUT_F) acc = di * di * g_h2[(size_t)node * 8 + o];

    int beg = g_rowstart[node];
    int end = g_rowstart[node + 1];
    for (int e = beg + g; e < end; e += 4) {
        int s = g_srcs[e];
        float w = g_dinv[s] * di;
        if (o < OUT_F) acc = fmaf(w, g_h2[(size_t)s * 8 + o], acc);
    }
    acc += __shfl_xor_sync(0xffffffffu, acc, 8);
    acc += __shfl_xor_sync(0xffffffffu, acc, 16);

    if (lane < OUT_F) out[(size_t)node * OUT_F + lane] = acc + b2[lane];
}

// ---------------- launch: R9 fork-join schedule ------------------------------
extern "C" void kernel_launch(void* const* d_in, const int* in_sizes, int n_in,
                              void* d_out, int out_size) {
    const float* x  = nullptr;
    const int*   ei = nullptr;
    const float* W1 = nullptr;
    const float* b1 = nullptr;
    const float* W2 = nullptr;
    const float* b2 = nullptr;
    long long ei_elems = 0;

    for (int i = 0; i < n_in; i++) {
        long long sz = in_sizes[i];
        if      (sz == (long long)N_NODES * IN_F) x  = (const float*)d_in[i];
        else if (sz == (long long)IN_F * HID)     W1 = (const float*)d_in[i];
        else if (sz == HID)                       b1 = (const float*)d_in[i];
        else if (sz == HID * OUT_F)               W2 = (const float*)d_in[i];
        else if (sz == OUT_F)                     b2 = (const float*)d_in[i];
        else { ei = (const int*)d_in[i]; ei_elems = sz; }
    }

    int E = (int)(ei_elems / 2);
    if (E > E_EDGES) E = E_EDGES;
    float* out = (float*)d_out;
    int eth = (E + 3) / 4;

    // Side stream + fork/join events: created once, reused (host objects only).
    static cudaStream_t s1 = nullptr;
    static cudaEvent_t evFork = nullptr, evJoin = nullptr;
    if (!s1) {
        cudaStreamCreateWithFlags(&s1, cudaStreamNonBlocking);
        cudaEventCreateWithFlags(&evFork, cudaEventDisableTiming);
        cudaEventCreateWithFlags(&evJoin, cudaEventDisableTiming);
    }

    // Main stream: setup -> gemm1 -> (join) -> gather1 -> gather2
    // Side stream: (fork) -> hist -> scanA -> scanB -> scanC -> fill
    setup_kernel<<<NSCANB, 256>>>(W1, ei);                                 // 0
    cudaEventRecord(evFork, 0);
    cudaStreamWaitEvent(s1, evFork, 0);
    hist_kernel<<<(eth + 255) / 256, 256, 0, s1>>>(ei, E);                 // 1
    scanA_kernel<<<NSCANB, 256, 0, s1>>>();                                // 2
    gemm1_mma_kernel<<<GBLOCKS, 128>>>(x);                                 // 3 (profiled)
    scanB_kernel<<<1, 256, 0, s1>>>();                                     // 4
    scanC_kernel<<<NSCANB, 256, 0, s1>>>();                                // 5
    fill_kernel<<<(eth + 255) / 256, 256, 0, s1>>>(ei, E);                 // 6
    cudaEventRecord(evJoin, s1);
    cudaStreamWaitEvent(0, evJoin, 0);
    gather1_kernel<<<(N_NODES + 7) / 8, 256>>>(W2, b1);                    // 7
    gather2_kernel<<<(N_NODES + 7) / 8, 256>>>(b2, out);                   // 8
}

// round 12
// speedup vs baseline: 1.1155x; 1.1155x over previous
#include <cuda_runtime.h>
#include <cuda_fp16.h>
#include <cuda_bf16.h>
#include <cstdint>

#define N_NODES 50000
#define E_EDGES 1600000
#define IN_F 512
#define HID 64
#define OUT_F 7
#define KSTEPS 32                // 512 / 16
#define NTILES 8                 // 64 / 8
#define MWARPS 3125              // 50000 / 16 rows per warp
#define NSCANB 196               // ceil(50000 / 256)

// ---------------- scratch (static device globals; no allocation) -------------
__device__ float    g_dinv[N_NODES];
__device__ int      g_count[N_NODES];
__device__ int      g_rowstart[N_NODES + 1];
__device__ int      g_cursor[N_NODES];
__device__ int      g_srcs[E_EDGES];
__device__ uint32_t g_h1h[(size_t)N_NODES * 32];   // h1 as half2 pairs: [node][f/2]
__device__ float    g_h2[(size_t)N_NODES * 8];     // relu(agg1+b1) @ W2, stride 8
__device__ int      g_is64;                        // edge_index dtype flag
__device__ int      g_blocksum[NSCANB];
__device__ int      g_blockoff[NSCANB];
// Pre-packed W1 fragments, layout [ks][nt][lane], K-permuted (see w1 pack)
__device__ uint2 g_bfragH[KSTEPS * NTILES * 32];
__device__ uint2 g_bfragL[KSTEPS * NTILES * 32];

// ---------------- helpers ----------------------------------------------------
__device__ __forceinline__ void mma16816(float* d, const uint32_t* a, const uint32_t b0,
                                         const uint32_t b1) {
    asm volatile(
        "mma.sync.aligned.m16n8k16.row.col.f32.bf16.bf16.f32 "
        "{%0,%1,%2,%3}, {%4,%5,%6,%7}, {%8,%9}, {%0,%1,%2,%3};"
        : "+f"(d[0]), "+f"(d[1]), "+f"(d[2]), "+f"(d[3])
        : "r"(a[0]), "r"(a[1]), "r"(a[2]), "r"(a[3]), "r"(b0), "r"(b1));
}

// fast split: hi = bf16x2(fa@lo, fb@hi); lo = residuals
__device__ __forceinline__ void cvt_pair(float fa, float fb, uint32_t& hi, uint32_t& lo) {
    asm("cvt.rn.bf16x2.f32 %0, %1, %2;" : "=r"(hi) : "f"(fb), "f"(fa));
    float ra = __uint_as_float(hi << 16);
    float rb = __uint_as_float(hi & 0xffff0000u);
    float la = fa - ra, lb = fb - rb;
    asm("cvt.rn.bf16x2.f32 %0, %1, %2;" : "=r"(lo) : "f"(lb), "f"(la));
}

// ---------------- setup: zero counts + detect dtype + pack W1 frags ----------
// K-permutation: for kstep ks, lane tg group, virtual k {2tg,2tg+1,2tg+8,2tg+9}
// maps to physical k {kb..kb+3}, kb = ks*16 + tg*4. A-side loads use the same
// permutation, so results are exact.
__global__ void setup_kernel(const float* __restrict__ W1, const int* __restrict__ ei32) {
    int idx = blockIdx.x * blockDim.x + threadIdx.x;
    if (idx < N_NODES) g_count[idx] = 0;
    if (idx < KSTEPS * NTILES * 32) {
        int lane = idx & 31;
        int t    = idx >> 5;
        int nt   = t & 7;
        int ks   = t >> 3;
        int tg = lane & 3, gp = lane >> 2;
        int n  = nt * 8 + gp;
        int kb = ks * 16 + tg * 4;
        float f00 = W1[(size_t)(kb)     * HID + n];
        float f01 = W1[(size_t)(kb + 1) * HID + n];
        float f10 = W1[(size_t)(kb + 2) * HID + n];
        float f11 = W1[(size_t)(kb + 3) * HID + n];
        uint32_t h0, l0, h1, l1;
        cvt_pair(f00, f01, h0, l0);
        cvt_pair(f10, f11, h1, l1);
        g_bfragH[idx] = make_uint2(h0, h1);
        g_bfragL[idx] = make_uint2(l0, l1);
    }
    if (blockIdx.x == 0 && idx < 32) {
        int nz = (ei32[2 * idx + 1] != 0) | (ei32[2 * (idx + 32) + 1] != 0);
        unsigned any = __ballot_sync(0xffffffffu, nz);
        if (idx == 0) g_is64 = (any == 0);
    }
}

__device__ __forceinline__ int load_idx(const int* ei32, long long pos, int is64) {
    if (is64) {
        const long long* p = (const long long*)ei32;
        return (int)p[pos];
    }
    return ei32[pos];
}

// ---------------- degree histogram (4 edges / thread) ------------------------
__global__ void hist_kernel(const int* __restrict__ ei32, int E) {
    int e0 = (blockIdx.x * blockDim.x + threadIdx.x) * 4;
    if (e0 >= E) return;
    int is64 = g_is64;
    int d[4];
    int n = min(4, E - e0);
    if (n == 4 && (E & 3) == 0) {
        if (is64) {
            const longlong2* p = (const longlong2*)((const long long*)ei32 + E + e0);
            longlong2 v0 = p[0], v1 = p[1];
            d[0] = (int)v0.x; d[1] = (int)v0.y; d[2] = (int)v1.x; d[3] = (int)v1.y;
        } else {
            int4 v = *(const int4*)(ei32 + E + e0);
            d[0] = v.x; d[1] = v.y; d[2] = v.z; d[3] = v.w;
        }
    } else {
        for (int i = 0; i < 4; i++)
            d[i] = (i < n) ? load_idx(ei32, (long long)E + e0 + i, is64) : -1;
    }
#pragma unroll
    for (int i = 0; i < 4; i++) {
        unsigned dd = (unsigned)d[i];
        if (dd < N_NODES) atomicAdd(&g_count[dd], 1);
    }
}

// ---------------- 3-phase parallel exclusive scan ----------------------------
__global__ void scanA_kernel() {            // per-block reduction of counts
    __shared__ int red[256];
    int i = blockIdx.x * 256 + threadIdx.x;
    int c = (i < N_NODES) ? g_count[i] : 0;
    red[threadIdx.x] = c;
    __syncthreads();
    for (int off = 128; off; off >>= 1) {
        if (threadIdx.x < off) red[threadIdx.x] += red[threadIdx.x + off];
        __syncthreads();
    }
    if (threadIdx.x == 0) g_blocksum[blockIdx.x] = red[0];
}

__global__ void scanB_kernel() {            // scan 196 block sums (1 block)
    __shared__ int s[256];
    int tid = threadIdx.x;
    int v = (tid < NSCANB) ? g_blocksum[tid] : 0;
    s[tid] = v;
    __syncthreads();
    for (int off = 1; off < 256; off <<= 1) {
        int t = (tid >= off) ? s[tid - off] : 0;
        __syncthreads();
        s[tid] += t;
        __syncthreads();
    }
    if (tid < NSCANB) g_blockoff[tid] = s[tid] - v;   // exclusive
}

__global__ void scanC_kernel() {            // block-local scan + apply + dinv
    __shared__ int s[256];
    int tid = threadIdx.x;
    int i = blockIdx.x * 256 + tid;
    int c = (i < N_NODES) ? g_count[i] : 0;
    s[tid] = c;
    __syncthreads();
    for (int off = 1; off < 256; off <<= 1) {
        int t = (tid >= off) ? s[tid - off] : 0;
        __syncthreads();
        s[tid] += t;
        __syncthreads();
    }
    if (i < N_NODES) {
        int excl = g_blockoff[blockIdx.x] + s[tid] - c;
        g_rowstart[i] = excl;
        g_cursor[i]   = excl;
        g_dinv[i]     = rsqrtf((float)(c + 1));       // deg includes self-loop
        if (i == N_NODES - 1) g_rowstart[N_NODES] = excl + c;
    }
}

// ---------------- CSR fill (4 edges / thread) --------------------------------
__global__ void fill_kernel(const int* __restrict__ ei32, int E) {
    int e0 = (blockIdx.x * blockDim.x + threadIdx.x) * 4;
    if (e0 >= E) return;
    int is64 = g_is64;
    int sr[4], d[4];
    int n = min(4, E - e0);
    if (n == 4 && (E & 3) == 0) {
        if (is64) {
            const longlong2* ps = (const longlong2*)((const long long*)ei32 + e0);
            const longlong2* pd = (const longlong2*)((const long long*)ei32 + E + e0);
            longlong2 s0 = ps[0], s1 = ps[1], v0 = pd[0], v1 = pd[1];
            sr[0] = (int)s0.x; sr[1] = (int)s0.y; sr[2] = (int)s1.x; sr[3] = (int)s1.y;
            d[0] = (int)v0.x;  d[1] = (int)v0.y;  d[2] = (int)v1.x;  d[3] = (int)v1.y;
        } else {
            int4 s = *(const int4*)(ei32 + e0);
            int4 v = *(const int4*)(ei32 + E + e0);
            sr[0] = s.x; sr[1] = s.y; sr[2] = s.z; sr[3] = s.w;
            d[0] = v.x;  d[1] = v.y;  d[2] = v.z;  d[3] = v.w;
        }
    } else {
        for (int i = 0; i < 4; i++) {
            sr[i] = (i < n) ? load_idx(ei32, e0 + i, is64) : -1;
            d[i]  = (i < n) ? load_idx(ei32, (long long)E + e0 + i, is64) : -1;
        }
    }
#pragma unroll
    for (int i = 0; i < 4; i++) {
        unsigned ss = (unsigned)sr[i], dd = (unsigned)d[i];
        if (ss < N_NODES && dd < N_NODES) {
            int pos = atomicAdd(&g_cursor[dd], 1);
            if (pos < E_EDGES) g_srcs[pos] = (int)ss;
        }
    }
}

// ---------------- GEMM1 (R9-proven): 16 rows/warp, depth-1 prefetch ----------
// D = xh*wh + xh*wl + xl*wh, fp32 accumulate; h1 stored as fp16 pairs.
__global__ __launch_bounds__(128) void gemm1_mma_kernel(const float* __restrict__ x) {
    int wg   = (blockIdx.x * blockDim.x + threadIdx.x) >> 5;
    int lane = threadIdx.x & 31;
    if (wg >= MWARPS) return;

    int gp = lane >> 2, tg = lane & 3;
    int r0 = wg * 16 + gp, r1 = r0 + 8;

    const float4* pa = (const float4*)(x + (size_t)r0 * IN_F) + tg;
    const float4* pb = (const float4*)(x + (size_t)r1 * IN_F) + tg;

    float acc[NTILES][4];
#pragma unroll
    for (int nt = 0; nt < NTILES; nt++)
#pragma unroll
        for (int j = 0; j < 4; j++) acc[nt][j] = 0.f;

    float4 va = pa[0];
    float4 vb = pb[0];

    for (int ks = 0; ks < KSTEPS; ks++) {
        uint32_t ah[4], al[4];
        cvt_pair(va.x, va.y, ah[0], al[0]);
        cvt_pair(vb.x, vb.y, ah[1], al[1]);
        cvt_pair(va.z, va.w, ah[2], al[2]);
        cvt_pair(vb.z, vb.w, ah[3], al[3]);

        float4 va_n, vb_n;
        if (ks + 1 < KSTEPS) {
            va_n = pa[(ks + 1) * 4];
            vb_n = pb[(ks + 1) * 4];
        }

        const uint2* fh = &g_bfragH[(ks * NTILES) * 32 + lane];
        const uint2* fl = &g_bfragL[(ks * NTILES) * 32 + lane];
#pragma unroll
        for (int nt = 0; nt < NTILES; nt++) {
            uint2 wh = __ldg(fh + nt * 32);
            uint2 wl = __ldg(fl + nt * 32);
            mma16816(acc[nt], ah, wh.x, wh.y);
            mma16816(acc[nt], ah, wl.x, wl.y);
            mma16816(acc[nt], al, wh.x, wh.y);
        }
        va = va_n;
        vb = vb_n;
    }

    // epilogue: columns (nt*8+tg*2, +1) -> half2 slot nt*4+tg
#pragma unroll
    for (int nt = 0; nt < NTILES; nt++) {
        int cslot = nt * 4 + tg;
        __half2 h0 = __float22half2_rn(make_float2(acc[nt][0], acc[nt][1]));
        __half2 h1v = __float22half2_rn(make_float2(acc[nt][2], acc[nt][3]));
        g_h1h[(size_t)r0 * 32 + cslot] = *(uint32_t*)&h0;
        g_h1h[(size_t)r1 * 32 + cslot] = *(uint32_t*)&h1v;
    }
}

// ---------------- gather1: agg1(h1 fp16) -> relu(+b1) -> fused @W2 -> h2 -----
// One warp per node; lane owns features (2*lane, 2*lane+1) = one half2.
// 8-edge unroll -> 8 outstanding half2 loads per warp.
__global__ __launch_bounds__(256) void gather1_kernel(const float* __restrict__ W2,
                                                      const float* __restrict__ b1) {
    int node = (blockIdx.x * blockDim.x + threadIdx.x) >> 5;
    int lane = threadIdx.x & 31;
    if (node >= N_NODES) return;

    float di = g_dinv[node];
    float self_w = di * di;
    {
    }
    uint32_t selfp = g_h1h[(size_t)node * 32 + lane];
    float2 sf = __half22float2(*(__half2*)&selfp);
    float a0[4], a1[4];
    a0[0] = sf.x * self_w; a1[0] = sf.y * self_w;
    a0[1] = a0[2] = a0[3] = 0.f;
    a1[1] = a1[2] = a1[3] = 0.f;

    int beg = g_rowstart[node];
    int end = g_rowstart[node + 1];
    for (int e = beg; e < end; e += 32) {
        int s = 0; float w = 0.f;
        if (e + lane < end) {
            s = g_srcs[e + lane];
            w = g_dinv[s] * di;
        }
        int cnt = min(32, end - e);
        int j = 0;
        for (; j + 8 <= cnt; j += 8) {
            int   sj[8]; float wj[8]; uint32_t hv[8];
#pragma unroll
            for (int k = 0; k < 8; k++) {
                sj[k] = __shfl_sync(0xffffffffu, s, j + k);
                wj[k] = __shfl_sync(0xffffffffu, w, j + k);
            }
#pragma unroll
            for (int k = 0; k < 8; k++)
                hv[k] = g_h1h[(size_t)sj[k] * 32 + lane];
#pragma unroll
            for (int k = 0; k < 8; k++) {
                float2 f = __half22float2(*(__half2*)&hv[k]);
                a0[k & 3] = fmaf(f.x, wj[k], a0[k & 3]);
                a1[k & 3] = fmaf(f.y, wj[k], a1[k & 3]);
            }
        }
        for (; j < cnt; j++) {
            int   ss = __shfl_sync(0xffffffffu, s, j);
            float ww = __shfl_sync(0xffffffffu, w, j);
            uint32_t hv = g_h1h[(size_t)ss * 32 + lane];
            float2 f = __half22float2(*(__half2*)&hv);
            a0[0] = fmaf(f.x, ww, a0[0]);
            a1[0] = fmaf(f.y, ww, a1[0]);
        }
    }

    float v0 = (a0[0] + a0[1]) + (a0[2] + a0[3]);
    float v1 = (a1[0] + a1[1]) + (a1[2] + a1[3]);
    int f0 = 2 * lane, f1 = 2 * lane + 1;
    v0 = fmaxf(v0 + b1[f0], 0.f);
    v1 = fmaxf(v1 + b1[f1], 0.f);

    float acc[OUT_F];
#pragma unroll
    for (int o = 0; o < OUT_F; o++)
        acc[o] = v0 * __ldg(&W2[f0 * OUT_F + o]) +
                 v1 * __ldg(&W2[f1 * OUT_F + o]);
#pragma unroll
    for (int off = 16; off; off >>= 1)
#pragma unroll
        for (int o = 0; o < OUT_F; o++)
            acc[o] += __shfl_xor_sync(0xffffffffu, acc[o], off);

    if (lane == 0) {
#pragma unroll
        for (int o = 0; o < OUT_F; o++) g_h2[(size_t)node * 8 + o] = acc[o];
    }
}

// ---------------- gather2: out = agg2(h2) + b2 -------------------------------
__global__ __launch_bounds__(256) void gather2_kernel(const float* __restrict__ b2,
                                                      float* __restrict__ out) {
    int node = (blockIdx.x * blockDim.x + threadIdx.x) >> 5;
    int lane = threadIdx.x & 31;
    if (node >= N_NODES) return;

    int o = lane & 7;
    int g = lane >> 3;
    float di = g_dinv[node];

    float acc = 0.f;
    if (g == 0 && o < OUT_F) acc = di * di * g_h2[(size_t)node * 8 + o];

    int beg = g_rowstart[node];
    int end = g_rowstart[node + 1];
    for (int e = beg + g; e < end; e += 4) {
        int s = g_srcs[e];
        float w = g_dinv[s] * di;
        if (o < OUT_F) acc = fmaf(w, g_h2[(size_t)s * 8 + o], acc);
    }
    acc += __shfl_xor_sync(0xffffffffu, acc, 8);
    acc += __shfl_xor_sync(0xffffffffu, acc, 16);

    if (lane < OUT_F) out[(size_t)node * OUT_F + lane] = acc + b2[lane];
}

// ---------------- launch: R9 fork-join schedule ------------------------------
extern "C" void kernel_launch(void* const* d_in, const int* in_sizes, int n_in,
                              void* d_out, int out_size) {
    const float* x  = nullptr;
    const int*   ei = nullptr;
    const float* W1 = nullptr;
    const float* b1 = nullptr;
    const float* W2 = nullptr;
    const float* b2 = nullptr;
    long long ei_elems = 0;

    for (int i = 0; i < n_in; i++) {
        long long sz = in_sizes[i];
        if      (sz == (long long)N_NODES * IN_F) x  = (const float*)d_in[i];
        else if (sz == (long long)IN_F * HID)     W1 = (const float*)d_in[i];
        else if (sz == HID)                       b1 = (const float*)d_in[i];
        else if (sz == HID * OUT_F)               W2 = (const float*)d_in[i];
        else if (sz == OUT_F)                     b2 = (const float*)d_in[i];
        else { ei = (const int*)d_in[i]; ei_elems = sz; }
    }

    int E = (int)(ei_elems / 2);
    if (E > E_EDGES) E = E_EDGES;
    float* out = (float*)d_out;
    int eth = (E + 3) / 4;

    // Side stream + fork/join events: created once, reused (host objects only).
    static cudaStream_t s1 = nullptr;
    static cudaEvent_t evFork = nullptr, evJoin = nullptr;
    if (!s1) {
        cudaStreamCreateWithFlags(&s1, cudaStreamNonBlocking);
        cudaEventCreateWithFlags(&evFork, cudaEventDisableTiming);
        cudaEventCreateWithFlags(&evJoin, cudaEventDisableTiming);
    }

    // Main stream: setup -> gemm1 -> (join) -> gather1 -> gather2
    // Side stream: (fork) -> hist -> scanA -> scanB -> scanC -> fill
    setup_kernel<<<NSCANB, 256>>>(W1, ei);                                 // 0
    cudaEventRecord(evFork, 0);
    cudaStreamWaitEvent(s1, evFork, 0);
    hist_kernel<<<(eth + 255) / 256, 256, 0, s1>>>(ei, E);                 // 1
    scanA_kernel<<<NSCANB, 256, 0, s1>>>();                                // 2
    gemm1_mma_kernel<<<(MWARPS * 32 + 127) / 128, 128>>>(x);               // 3 (profiled)
    scanB_kernel<<<1, 256, 0, s1>>>();                                     // 4
    scanC_kernel<<<NSCANB, 256, 0, s1>>>();                                // 5
    fill_kernel<<<(eth + 255) / 256, 256, 0, s1>>>(ei, E);                 // 6
    cudaEventRecord(evJoin, s1);
    cudaStreamWaitEvent(0, evJoin, 0);
    gather1_kernel<<<(N_NODES + 7) / 8, 256>>>(W2, b1);                    // 7
    gather2_kernel<<<(N_NODES + 7) / 8, 256>>>(b2, out);                   // 8
}